// round 1
// baseline (speedup 1.0000x reference)
#include <cuda_runtime.h>
#include <cuda_bf16.h>

// Problem constants
#define BN     4096
#define KN     20
#define D_NODE 172
#define D_EDGE 172
#define D_TIME 100
#define D_EMB  128
#define M_MSG  (BN * KN)      // 81920
#define BM     64             // rows per block tile
#define XS_STR 66             // padded smem row stride (floats), keeps 8B align + low conflicts

// Scratch (device globals — no allocation allowed)
__device__ float g_msg[M_MSG * D_EMB];     // ~42 MB: per-(b,k) message pre-mask (node+edge+time proj)
__device__ float g_hsrc[BN * D_EMB];       // 2 MB: node_proj(src) (memory added in combine)
__device__ float g_stime[D_EMB];           // src time embedding (batch-invariant)

// ---------------- accurate cos for large fp32 args (Cody-Waite, fma-based) ----------------
__device__ __forceinline__ float cos_cw(float x) {
    const float TWO_OVER_PI = 0.63661977236758134f;
    const float P1 = 1.57079625129699707031e+00f;  // 0x3FC90FDA
    const float P2 = 7.54978941586159375e-08f;     // 0x33A22168
    const float P3 = 5.39030252995776477e-15f;
    float n = rintf(x * TWO_OVER_PI);
    float r = fmaf(n, -P1, x);
    r = fmaf(n, -P2, r);
    r = fmaf(n, -P3, r);
    int q = ((int)n) & 3;
    float r2 = r * r;
    // sin poly on [-~0.82, ~0.82]
    float s = fmaf(r2, -1.98412698412698413e-4f, 8.33333333333333322e-3f);
    s = fmaf(r2, s, -1.66666666666666666e-1f);
    s = r * fmaf(r2, s, 1.0f);
    // cos poly
    float c = fmaf(r2, 2.48015873015873016e-5f, -1.38888888888888889e-3f);
    c = fmaf(r2, c, 4.16666666666666666e-2f);
    c = fmaf(r2, c, -0.5f);
    c = fmaf(r2, c, 1.0f);
    float v = (q & 1) ? s : c;
    if ((q + 1) & 2) v = -v;
    return v;
}

// ---------------- f32x2 packed helpers ----------------
__device__ __forceinline__ unsigned long long dup2(float v) {
    unsigned long long r;
    asm("mov.b64 %0, {%1, %1};" : "=l"(r) : "f"(v));
    return r;
}
__device__ __forceinline__ void fma2(unsigned long long& d, unsigned long long a, unsigned long long b) {
    asm("fma.rn.f32x2 %0, %1, %2, %0;" : "+l"(d) : "l"(a), "l"(b));
}
__device__ __forceinline__ void unpack2(unsigned long long v, float& lo, float& hi) {
    asm("mov.b64 {%0, %1}, %2;" : "=f"(lo), "=f"(hi) : "l"(v));
}

// ---------------- GEMM inner: acc[p][c] over one weight phase ----------------
// xs layout: xs[k * XS_STR + r]  (k-major, rows contiguous -> LDS.64 gives packed row pair)
__device__ __forceinline__ void mma_phase(const float* __restrict__ W, int KD,
                                          const float* xs, int r0, int c0,
                                          unsigned long long acc[16]) {
    #pragma unroll 2
    for (int k = 0; k < KD; k++) {
        const float4 w4 = *reinterpret_cast<const float4*>(W + k * D_EMB + c0);
        unsigned long long w0 = dup2(w4.x), w1 = dup2(w4.y), w2 = dup2(w4.z), w3 = dup2(w4.w);
        const float* xk = xs + k * XS_STR + r0;
        #pragma unroll
        for (int p = 0; p < 4; p++) {
            unsigned long long x2 = *reinterpret_cast<const unsigned long long*>(xk + 2 * p);
            fma2(acc[p * 4 + 0], x2, w0);
            fma2(acc[p * 4 + 1], x2, w1);
            fma2(acc[p * 4 + 2], x2, w2);
            fma2(acc[p * 4 + 3], x2, w3);
        }
    }
}

__device__ __forceinline__ void fill_gather(float* xs, const float* __restrict__ base, int D,
                                            const int* idx_s, int wid, int lane) {
    for (int r = wid; r < BM; r += 8) {
        const float* src = base + (size_t)idx_s[r] * D;
        for (int k = lane; k < D; k += 32) xs[k * XS_STR + r] = src[k];
    }
}

// ---------------- fused projection GEMM ----------------
// is_src==0: rows = B*K messages, phases node+edge+time  -> g_msg
// is_src==1: rows = B sources,   phase node only          -> g_hsrc
__global__ void __launch_bounds__(256, 2) proj_kernel(
    const float* __restrict__ node_features, const float* __restrict__ edge_features,
    const float* __restrict__ timestamps, const float* __restrict__ edge_times,
    const float* __restrict__ time_w, const float* __restrict__ time_b,
    const float* __restrict__ W_node, const float* __restrict__ W_edge,
    const float* __restrict__ W_time,
    const int* __restrict__ source_nodes, const int* __restrict__ neighbors,
    const int* __restrict__ edge_idxs, int is_src)
{
    __shared__ float xs[D_NODE * XS_STR];   // 172*66*4 = 45408 B (reused per phase)
    __shared__ int   nidx_s[BM];
    __shared__ int   eidx_s[BM];
    __shared__ float delta_s[BM];

    const int tid = threadIdx.x;
    const int lane = tid & 31;
    const int wid = tid >> 5;
    const int m0 = blockIdx.x * BM;
    const int r0 = wid * 8;       // 8 rows per warp-group thread-row
    const int c0 = lane * 4;      // 4 cols per lane

    if (tid < BM) {
        int gr = m0 + tid;
        if (is_src) {
            nidx_s[tid] = source_nodes[gr];
        } else {
            nidx_s[tid] = neighbors[gr];
            eidx_s[tid] = edge_idxs[gr];
            delta_s[tid] = timestamps[gr / KN] - edge_times[gr];
        }
    }
    __syncthreads();

    unsigned long long acc[16];
    #pragma unroll
    for (int i = 0; i < 16; i++) acc[i] = 0ULL;

    // ---- phase 1: node features ----
    fill_gather(xs, node_features, D_NODE, nidx_s, wid, lane);
    __syncthreads();
    mma_phase(W_node, D_NODE, xs, r0, c0, acc);

    if (!is_src) {
        // ---- phase 2: edge features ----
        __syncthreads();
        fill_gather(xs, edge_features, D_EDGE, eidx_s, wid, lane);
        __syncthreads();
        mma_phase(W_edge, D_EDGE, xs, r0, c0, acc);
        __syncthreads();
        // ---- phase 3: time encoding ----
        for (int r = wid; r < BM; r += 8) {
            float d = delta_s[r];
            for (int j = lane; j < D_TIME; j += 32) {
                // match reference: (t*w) + b, two separate roundings (no contraction)
                float arg = __fadd_rn(__fmul_rn(d, time_w[j]), time_b[j]);
                xs[j * XS_STR + r] = cos_cw(arg);
            }
        }
        __syncthreads();
        mma_phase(W_time, D_TIME, xs, r0, c0, acc);
    }

    float* out = is_src ? g_hsrc : g_msg;
    #pragma unroll
    for (int p = 0; p < 4; p++) {
        float4 ra, rb;
        unpack2(acc[p * 4 + 0], ra.x, rb.x);
        unpack2(acc[p * 4 + 1], ra.y, rb.y);
        unpack2(acc[p * 4 + 2], ra.z, rb.z);
        unpack2(acc[p * 4 + 3], ra.w, rb.w);
        size_t row = (size_t)(m0 + r0 + 2 * p);
        *reinterpret_cast<float4*>(out + row * D_EMB + c0) = ra;
        *reinterpret_cast<float4*>(out + (row + 1) * D_EMB + c0) = rb;
    }
}

// ---------------- src time embedding: cos(b) @ W_time (batch-invariant) ----------------
__global__ void stime_kernel(const float* __restrict__ time_w, const float* __restrict__ time_b,
                             const float* __restrict__ W_time) {
    int c = threadIdx.x;  // 128
    float s = 0.f;
    for (int j = 0; j < D_TIME; j++) {
        float arg = __fadd_rn(__fmul_rn(0.f, time_w[j]), time_b[j]);
        s += cos_cw(arg) * W_time[j * D_EMB + c];
    }
    g_stime[c] = s;
}

// ---------------- combine: mask, mean, memory gathers, final sum ----------------
__global__ void __launch_bounds__(128) combine_kernel(
    const float* __restrict__ memory, const int* __restrict__ source_nodes,
    const int* __restrict__ neighbors, float* __restrict__ out)
{
    int b = blockIdx.x;
    int c = threadIdx.x;  // 128
    float agg = 0.f;
    int cnt = 0;
    #pragma unroll
    for (int k = 0; k < KN; k++) {
        int nbr = neighbors[b * KN + k];
        if (nbr != 0) {
            cnt++;
            agg += g_msg[(size_t)(b * KN + k) * D_EMB + c] + memory[(size_t)nbr * D_EMB + c];
        }
    }
    float cntf = (float)(cnt > 0 ? cnt : 1);
    int src = source_nodes[b];
    out[(size_t)b * D_EMB + c] = g_hsrc[(size_t)b * D_EMB + c]
                               + memory[(size_t)src * D_EMB + c]
                               + g_stime[c]
                               + agg / cntf;
}

extern "C" void kernel_launch(void* const* d_in, const int* in_sizes, int n_in,
                              void* d_out, int out_size) {
    const float* node_features = (const float*)d_in[0];
    const float* edge_features = (const float*)d_in[1];
    const float* memory        = (const float*)d_in[2];
    const float* timestamps    = (const float*)d_in[3];
    const float* edge_times    = (const float*)d_in[4];
    const float* time_w        = (const float*)d_in[5];
    const float* time_b        = (const float*)d_in[6];
    const float* W_node        = (const float*)d_in[7];
    const float* W_edge        = (const float*)d_in[8];
    const float* W_time        = (const float*)d_in[9];
    const int*   source_nodes  = (const int*)d_in[10];
    const int*   neighbors     = (const int*)d_in[11];
    const int*   edge_idxs     = (const int*)d_in[12];
    float* out = (float*)d_out;

    stime_kernel<<<1, 128>>>(time_w, time_b, W_time);
    proj_kernel<<<M_MSG / BM, 256>>>(node_features, edge_features, timestamps, edge_times,
                                     time_w, time_b, W_node, W_edge, W_time,
                                     source_nodes, neighbors, edge_idxs, 0);
    proj_kernel<<<BN / BM, 256>>>(node_features, edge_features, timestamps, edge_times,
                                  time_w, time_b, W_node, W_edge, W_time,
                                  source_nodes, neighbors, edge_idxs, 1);
    combine_kernel<<<BN, 128>>>(memory, source_nodes, neighbors, out);
}

// round 3
// speedup vs baseline: 2.2750x; 2.2750x over previous
#include <cuda_runtime.h>
#include <cuda_bf16.h>
#include <cstdint>

// ---------------- problem constants ----------------
#define BN      4096
#define KN      20
#define D_EMB   128
#define D_FEAT  172
#define D_TIME  100
#define XCOLS   448              // X row stride: node 172 | edge 172 | time 100 | pad 4
#define BM      32               // GEMM rows per block
#define XS_STR  34               // padded smem stride

typedef unsigned long long ull;

// ---------------- device scratch (no allocation allowed) ----------------
__device__ __align__(16) float g_X[(size_t)BN * XCOLS];     // 7.3 MB reduced features
__device__ __align__(16) float g_base[(size_t)BN * D_EMB];  // memory terms

// ---------------- accurate cos for large fp32 args (validated round 1) ----------------
__device__ __forceinline__ float cos_cw(float x) {
    const float TWO_OVER_PI = 0.63661977236758134f;
    const float P1 = 1.57079625129699707031e+00f;
    const float P2 = 7.54978941586159375e-08f;
    const float P3 = 5.39030252995776477e-15f;
    float n = rintf(x * TWO_OVER_PI);
    float r = fmaf(n, -P1, x);
    r = fmaf(n, -P2, r);
    r = fmaf(n, -P3, r);
    int q = ((int)n) & 3;
    float r2 = r * r;
    float s = fmaf(r2, -1.98412698412698413e-4f, 8.33333333333333322e-3f);
    s = fmaf(r2, s, -1.66666666666666666e-1f);
    s = r * fmaf(r2, s, 1.0f);
    float c = fmaf(r2, 2.48015873015873016e-5f, -1.38888888888888889e-3f);
    c = fmaf(r2, c, 4.16666666666666666e-2f);
    c = fmaf(r2, c, -0.5f);
    c = fmaf(r2, c, 1.0f);
    float v = (q & 1) ? s : c;
    if ((q + 1) & 2) v = -v;
    return v;
}

// ---------------- f32x2 packed helpers (validated round 1) ----------------
__device__ __forceinline__ ull dup2(float v) {
    ull r;
    asm("mov.b64 %0, {%1, %1};" : "=l"(r) : "f"(v));
    return r;
}
__device__ __forceinline__ void fma2(ull& d, ull a, ull b) {
    asm("fma.rn.f32x2 %0, %1, %2, %0;" : "+l"(d) : "l"(a), "l"(b));
}
__device__ __forceinline__ void unpack2(ull v, float& lo, float& hi) {
    asm("mov.b64 {%0, %1}, %2;" : "=f"(lo), "=f"(hi) : "l"(v));
}

// ---------------- gather + masked reduce over K neighbors ----------------
// Column task space [0,572): [0,172) node | [172,344) edge | [344,444) time | [444,572) memory
// Thread t handles tasks t, t+256, t+512.
__global__ void __launch_bounds__(256) gather_kernel(
    const float* __restrict__ nf, const float* __restrict__ ef,
    const float* __restrict__ mem,
    const float* __restrict__ ts, const float* __restrict__ ets,
    const float* __restrict__ tw, const float* __restrict__ tb,
    const int* __restrict__ srcn, const int* __restrict__ nbr,
    const int* __restrict__ eidx)
{
    const int b = blockIdx.x;
    const int t = threadIdx.x;
    __shared__ int   nbr_s[KN];
    __shared__ int   eidx_s[KN];
    __shared__ float del_s[KN];

    if (t < KN) {
        nbr_s[t]  = nbr[b * KN + t];
        eidx_s[t] = eidx[b * KN + t];
        del_s[t]  = ts[b] - ets[b * KN + t];
    }
    __syncthreads();

    const int task1 = t + 256;
    const bool r0_node = (t < D_FEAT);          // else edge col t-172
    const bool r1_edge = (task1 < 344);          // edge col task1-172
    const bool r1_time = (task1 >= 344 && task1 < 444);
    const int  j       = task1 - 344;            // time col
    const bool r2_mem  = (t < 60);               // mem col t+68
    float wj = 0.f, bj = 0.f;
    if (r1_time) { wj = tw[j]; bj = tb[j]; }

    float acc0 = 0.f, acc1 = 0.f, acc2 = 0.f;
    int cnt = 0;

    #pragma unroll 4
    for (int k = 0; k < KN; k++) {
        const int nb = nbr_s[k];
        if (nb == 0) continue;
        cnt++;
        const int ei = eidx_s[k];
        // round 0: node cols 0..171 / edge cols 0..83
        if (r0_node) acc0 += __ldg(nf + (size_t)nb * D_FEAT + t);
        else         acc0 += __ldg(ef + (size_t)ei * D_FEAT + (t - D_FEAT));
        // round 1: edge cols 84..171 / time / mem cols 0..67
        if (r1_edge)      acc1 += __ldg(ef + (size_t)ei * D_FEAT + (task1 - D_FEAT));
        else if (r1_time) acc1 += cos_cw(__fadd_rn(__fmul_rn(del_s[k], wj), bj));
        else              acc1 += __ldg(mem + (size_t)nb * D_EMB + (task1 - 444));
        // round 2: mem cols 68..127
        if (r2_mem) acc2 += __ldg(mem + (size_t)nb * D_EMB + (t + 68));
    }

    const float inv = 1.f / (float)(cnt > 0 ? cnt : 1);
    const int src = srcn[b];

    // round-0 write: X column == task id for node/edge
    {
        float v = acc0 * inv;
        if (r0_node) v += __ldg(nf + (size_t)src * D_FEAT + t);
        g_X[(size_t)b * XCOLS + t] = v;
    }
    // round-1 write
    if (task1 < 444) {
        float v = acc1 * inv;
        if (r1_time) v += cos_cw(bj);   // src time embedding: cos(0*w + b) = cos(b)
        g_X[(size_t)b * XCOLS + task1] = v;
    } else {
        const int c = task1 - 444;
        g_base[(size_t)b * D_EMB + c] = __ldg(mem + (size_t)src * D_EMB + c) + acc1 * inv;
    }
    // round-2 write
    if (r2_mem) {
        const int c = t + 68;
        g_base[(size_t)b * D_EMB + c] = __ldg(mem + (size_t)src * D_EMB + c) + acc2 * inv;
    }
}

// ---------------- f32x2 GEMM: out = X @ [W_node; W_edge; W_time] + base ----------------
__device__ __forceinline__ void mma_phase(const float* __restrict__ W, int KD,
                                          const float* xs, int r0, int c0,
                                          ull acc[8]) {
    #pragma unroll 2
    for (int k = 0; k < KD; k++) {
        const float4 w4 = *reinterpret_cast<const float4*>(W + k * D_EMB + c0);
        ull w0 = dup2(w4.x), w1 = dup2(w4.y), w2 = dup2(w4.z), w3 = dup2(w4.w);
        const float* xk = xs + k * XS_STR + r0;
        #pragma unroll
        for (int p = 0; p < 2; p++) {
            ull x2 = *reinterpret_cast<const ull*>(xk + 2 * p);
            fma2(acc[p * 4 + 0], x2, w0);
            fma2(acc[p * 4 + 1], x2, w1);
            fma2(acc[p * 4 + 2], x2, w2);
            fma2(acc[p * 4 + 3], x2, w3);
        }
    }
}

__global__ void __launch_bounds__(256) gemm_kernel(
    const float* __restrict__ W_node, const float* __restrict__ W_edge,
    const float* __restrict__ W_time, float* __restrict__ out)
{
    __shared__ float xs[D_FEAT * XS_STR];   // 23392 B, reused per phase
    const int tid = threadIdx.x, wid = tid >> 5, lane = tid & 31;
    const int m0 = blockIdx.x * BM;
    const int r0 = wid * 4;        // 4 rows per warp
    const int c0 = lane * 4;       // 4 cols per lane

    ull acc[8];
    #pragma unroll
    for (int i = 0; i < 8; i++) acc[i] = 0ULL;

    const float* Ws[3]  = { W_node, W_edge, W_time };
    const int    Ds[3]  = { D_FEAT, D_FEAT, D_TIME };
    const int    off[3] = { 0, 172, 344 };

    #pragma unroll
    for (int ph = 0; ph < 3; ph++) {
        if (ph) __syncthreads();
        // fill xs[k][r] from contiguous X rows
        #pragma unroll
        for (int rr = 0; rr < 4; rr++) {
            const int r = wid * 4 + rr;
            const float* xr = g_X + (size_t)(m0 + r) * XCOLS + off[ph];
            for (int k = lane; k < Ds[ph]; k += 32) xs[k * XS_STR + r] = xr[k];
        }
        __syncthreads();
        mma_phase(Ws[ph], Ds[ph], xs, r0, c0, acc);
    }

    #pragma unroll
    for (int p = 0; p < 2; p++) {
        float4 ra, rb;
        unpack2(acc[p * 4 + 0], ra.x, rb.x);
        unpack2(acc[p * 4 + 1], ra.y, rb.y);
        unpack2(acc[p * 4 + 2], ra.z, rb.z);
        unpack2(acc[p * 4 + 3], ra.w, rb.w);
        const size_t rowA = (size_t)(m0 + r0 + 2 * p);
        const size_t rowB = rowA + 1;
        float4 bA = *(const float4*)&g_base[rowA * D_EMB + c0];
        float4 bB = *(const float4*)&g_base[rowB * D_EMB + c0];
        ra.x += bA.x; ra.y += bA.y; ra.z += bA.z; ra.w += bA.w;
        rb.x += bB.x; rb.y += bB.y; rb.z += bB.z; rb.w += bB.w;
        *(float4*)&out[rowA * D_EMB + c0] = ra;
        *(float4*)&out[rowB * D_EMB + c0] = rb;
    }
}

extern "C" void kernel_launch(void* const* d_in, const int* in_sizes, int n_in,
                              void* d_out, int out_size) {
    const float* node_features = (const float*)d_in[0];
    const float* edge_features = (const float*)d_in[1];
    const float* memory        = (const float*)d_in[2];
    const float* timestamps    = (const float*)d_in[3];
    const float* edge_times    = (const float*)d_in[4];
    const float* time_w        = (const float*)d_in[5];
    const float* time_b        = (const float*)d_in[6];
    const float* W_node        = (const float*)d_in[7];
    const float* W_edge        = (const float*)d_in[8];
    const float* W_time        = (const float*)d_in[9];
    const int*   source_nodes  = (const int*)d_in[10];
    const int*   neighbors     = (const int*)d_in[11];
    const int*   edge_idxs     = (const int*)d_in[12];
    float* out = (float*)d_out;

    gather_kernel<<<BN, 256>>>(node_features, edge_features, memory,
                               timestamps, edge_times, time_w, time_b,
                               source_nodes, neighbors, edge_idxs);
    gemm_kernel<<<BN / BM, 256>>>(W_node, W_edge, W_time, out);
}

// round 4
// speedup vs baseline: 3.6322x; 1.5966x over previous
#include <cuda_runtime.h>
#include <cuda_bf16.h>
#include <cstdint>

// ---------------- problem constants ----------------
#define BN      4096
#define KN      20
#define D_EMB   128
#define D_FEAT  172
#define D_TIME  100
#define XCOLS   448              // X row stride: node 172 | edge 172 | time 100 | pad 4
#define KTOT    448              // padded K for GEMM
#define GBM     8                // GEMM rows per block
#define XS_ST   10               // smem k-stride (floats): conflict-free, 8B-aligned pairs

typedef unsigned long long ull;

// ---------------- device scratch (no allocation allowed) ----------------
__device__ __align__(16) float g_X[(size_t)BN * XCOLS];     // 7.3 MB reduced features
__device__ __align__(16) float g_base[(size_t)BN * D_EMB];  // memory terms
__device__ __align__(16) float g_W[(size_t)KTOT * D_EMB];   // packed [Wn;We;Wt;0] 229 KB (L2-resident)

// ---------------- accurate cos for large fp32 args (validated) ----------------
__device__ __forceinline__ float cos_cw(float x) {
    const float TWO_OVER_PI = 0.63661977236758134f;
    const float P1 = 1.57079625129699707031e+00f;
    const float P2 = 7.54978941586159375e-08f;
    const float P3 = 5.39030252995776477e-15f;
    float n = rintf(x * TWO_OVER_PI);
    float r = fmaf(n, -P1, x);
    r = fmaf(n, -P2, r);
    r = fmaf(n, -P3, r);
    int q = ((int)n) & 3;
    float r2 = r * r;
    float s = fmaf(r2, -1.98412698412698413e-4f, 8.33333333333333322e-3f);
    s = fmaf(r2, s, -1.66666666666666666e-1f);
    s = r * fmaf(r2, s, 1.0f);
    float c = fmaf(r2, 2.48015873015873016e-5f, -1.38888888888888889e-3f);
    c = fmaf(r2, c, 4.16666666666666666e-2f);
    c = fmaf(r2, c, -0.5f);
    c = fmaf(r2, c, 1.0f);
    float v = (q & 1) ? s : c;
    if ((q + 1) & 2) v = -v;
    return v;
}

// ---------------- f32x2 packed helpers ----------------
__device__ __forceinline__ ull dup2(float v) {
    ull r;
    asm("mov.b64 %0, {%1, %1};" : "=l"(r) : "f"(v));
    return r;
}
__device__ __forceinline__ void fma2(ull& d, ull a, ull b) {
    asm("fma.rn.f32x2 %0, %1, %2, %0;" : "+l"(d) : "l"(a), "l"(b));
}
__device__ __forceinline__ void unpack2(ull v, float& lo, float& hi) {
    asm("mov.b64 {%0, %1}, %2;" : "=f"(lo), "=f"(hi) : "l"(v));
}

// ---------------- weight pack: g_W = [W_node; W_edge; W_time; zeros] ----------------
__global__ void __launch_bounds__(256) prep_W(
    const float* __restrict__ W_node, const float* __restrict__ W_edge,
    const float* __restrict__ W_time)
{
    int i = blockIdx.x * 256 + threadIdx.x;   // over 448*128 = 57344
    if (i >= KTOT * D_EMB) return;
    int k = i >> 7;
    int n = i & 127;
    float v;
    if (k < D_FEAT)            v = W_node[k * D_EMB + n];
    else if (k < 2 * D_FEAT)   v = W_edge[(k - D_FEAT) * D_EMB + n];
    else if (k < 2 * D_FEAT + D_TIME) v = W_time[(k - 2 * D_FEAT) * D_EMB + n];
    else                       v = 0.f;
    g_W[i] = v;
}

// ---------------- gather + masked reduce over K neighbors ----------------
// Column task space [0,572): [0,172) node | [172,344) edge | [344,444) time | [444,572) memory
// Thread t handles tasks t, t+256, t+512. Full unroll, mask-multiply (no branches in loop).
__global__ void __launch_bounds__(256) gather_kernel(
    const float* __restrict__ nf, const float* __restrict__ ef,
    const float* __restrict__ mem,
    const float* __restrict__ ts, const float* __restrict__ ets,
    const float* __restrict__ tw, const float* __restrict__ tb,
    const int* __restrict__ srcn, const int* __restrict__ nbr,
    const int* __restrict__ eidx)
{
    const int b = blockIdx.x;
    const int t = threadIdx.x;
    __shared__ int   nbr_s[KN];
    __shared__ int   eidx_s[KN];
    __shared__ float del_s[KN];
    __shared__ float msk_s[KN];

    if (t < KN) {
        int nb = nbr[b * KN + t];
        nbr_s[t]  = nb;
        eidx_s[t] = eidx[b * KN + t];
        del_s[t]  = ts[b] - ets[b * KN + t];
        msk_s[t]  = (nb != 0) ? 1.f : 0.f;
    }
    __syncthreads();

    const int task1 = t + 256;
    const bool r0_node = (t < D_FEAT);
    const bool r1_edge = (task1 < 344);
    const bool r1_time = (task1 >= 344 && task1 < 444);
    const int  j       = task1 - 344;
    const bool r2_mem  = (t < 60);
    float wj = 0.f, bj = 0.f;
    if (r1_time) { wj = tw[j]; bj = tb[j]; }

    float acc0 = 0.f, acc1 = 0.f, acc2 = 0.f;
    float cntf = 0.f;

    #pragma unroll
    for (int k = 0; k < KN; k++) {
        const float m  = msk_s[k];
        const int   nb = nbr_s[k];
        const int   ei = eidx_s[k];
        cntf += m;
        // round 0: node cols 0..171 / edge cols 0..83 (always load; mask-multiply)
        float v0 = r0_node ? __ldg(nf + (size_t)nb * D_FEAT + t)
                           : __ldg(ef + (size_t)ei * D_FEAT + (t - D_FEAT));
        acc0 = fmaf(m, v0, acc0);
        // round 1: edge cols 84..171 / time / mem cols 0..67
        float v1;
        if (r1_edge)      v1 = __ldg(ef + (size_t)ei * D_FEAT + (task1 - D_FEAT));
        else if (r1_time) v1 = cos_cw(__fadd_rn(__fmul_rn(del_s[k], wj), bj));
        else              v1 = __ldg(mem + (size_t)nb * D_EMB + (task1 - 444));
        acc1 = fmaf(m, v1, acc1);
        // round 2: mem cols 68..127
        if (r2_mem) acc2 = fmaf(m, __ldg(mem + (size_t)nb * D_EMB + (t + 68)), acc2);
    }

    const float inv = 1.f / fmaxf(cntf, 1.f);
    const int src = srcn[b];

    // round-0 write
    {
        float v = acc0 * inv;
        if (r0_node) v += __ldg(nf + (size_t)src * D_FEAT + t);
        g_X[(size_t)b * XCOLS + t] = v;
    }
    // round-1 write
    if (task1 < 444) {
        float v = acc1 * inv;
        if (r1_time) v += cos_cw(bj);   // src time embedding: cos(0*w + b)
        g_X[(size_t)b * XCOLS + task1] = v;
    } else {
        const int c = task1 - 444;
        g_base[(size_t)b * D_EMB + c] = __ldg(mem + (size_t)src * D_EMB + c) + acc1 * inv;
    }
    // round-2 write
    if (r2_mem) {
        const int c = t + 68;
        g_base[(size_t)b * D_EMB + c] = __ldg(mem + (size_t)src * D_EMB + c) + acc2 * inv;
    }
    // zero the 4 pad columns of X (keeps GEMM tail branch-free)
    if (t < 4) g_X[(size_t)b * XCOLS + 444 + t] = 0.f;
}

// ---------------- f32x2 GEMM: out = X @ g_W + base ----------------
// grid = 512 blocks x 128 threads. Block = 8 rows. Warp rp = row-pair (2rp, 2rp+1),
// lane covers cols [4*lane, 4*lane+4). Unroll 8 K-steps, W loads batched (MLP=8 on L2).
__global__ void __launch_bounds__(128) gemm_kernel(float* __restrict__ out)
{
    __shared__ float xs[KTOT * XS_ST];   // 17920 B, transposed X tile
    const int tid = threadIdx.x;
    const int rp = tid >> 5;             // warp id 0..3
    const int lane = tid & 31;
    const int c0 = lane * 4;
    const int m0 = blockIdx.x * GBM;

    // fill xs[k*XS_ST + row] from g_X (8 rows x 112 float4); STS pattern is conflict-free
    for (int idx = tid; idx < GBM * (KTOT / 4); idx += 128) {
        const int row = idx & 7;
        const int kb = (idx >> 3) << 2;
        float4 x = *(const float4*)&g_X[(size_t)(m0 + row) * XCOLS + kb];
        xs[(kb + 0) * XS_ST + row] = x.x;
        xs[(kb + 1) * XS_ST + row] = x.y;
        xs[(kb + 2) * XS_ST + row] = x.z;
        xs[(kb + 3) * XS_ST + row] = x.w;
    }
    __syncthreads();

    ull acc0 = 0ULL, acc1 = 0ULL, acc2 = 0ULL, acc3 = 0ULL;

    #pragma unroll 1
    for (int kb = 0; kb < KTOT; kb += 8) {
        float4 w[8];
        #pragma unroll
        for (int i = 0; i < 8; i++)
            w[i] = *(const float4*)&g_W[(size_t)(kb + i) * D_EMB + c0];
        #pragma unroll
        for (int i = 0; i < 8; i++) {
            ull x2 = *(const ull*)&xs[(kb + i) * XS_ST + 2 * rp];   // broadcast LDS.64
            fma2(acc0, x2, dup2(w[i].x));
            fma2(acc1, x2, dup2(w[i].y));
            fma2(acc2, x2, dup2(w[i].z));
            fma2(acc3, x2, dup2(w[i].w));
        }
    }

    float a0l, a0h, a1l, a1h, a2l, a2h, a3l, a3h;
    unpack2(acc0, a0l, a0h);
    unpack2(acc1, a1l, a1h);
    unpack2(acc2, a2l, a2h);
    unpack2(acc3, a3l, a3h);

    const size_t rA = (size_t)(m0 + 2 * rp) * D_EMB + c0;
    const size_t rB = rA + D_EMB;
    float4 bA = *(const float4*)&g_base[rA];
    float4 bB = *(const float4*)&g_base[rB];
    float4 oA = make_float4(a0l + bA.x, a1l + bA.y, a2l + bA.z, a3l + bA.w);
    float4 oB = make_float4(a0h + bB.x, a1h + bB.y, a2h + bB.z, a3h + bB.w);
    *(float4*)&out[rA] = oA;
    *(float4*)&out[rB] = oB;
}

extern "C" void kernel_launch(void* const* d_in, const int* in_sizes, int n_in,
                              void* d_out, int out_size) {
    const float* node_features = (const float*)d_in[0];
    const float* edge_features = (const float*)d_in[1];
    const float* memory        = (const float*)d_in[2];
    const float* timestamps    = (const float*)d_in[3];
    const float* edge_times    = (const float*)d_in[4];
    const float* time_w        = (const float*)d_in[5];
    const float* time_b        = (const float*)d_in[6];
    const float* W_node        = (const float*)d_in[7];
    const float* W_edge        = (const float*)d_in[8];
    const float* W_time        = (const float*)d_in[9];
    const int*   source_nodes  = (const int*)d_in[10];
    const int*   neighbors     = (const int*)d_in[11];
    const int*   edge_idxs     = (const int*)d_in[12];
    float* out = (float*)d_out;

    prep_W<<<(KTOT * D_EMB + 255) / 256, 256>>>(W_node, W_edge, W_time);
    gather_kernel<<<BN, 256>>>(node_features, edge_features, memory,
                               timestamps, edge_times, time_w, time_b,
                               source_nodes, neighbors, edge_idxs);
    gemm_kernel<<<BN / GBM, 128>>>(out);
}

// round 5
// speedup vs baseline: 4.7476x; 1.3071x over previous
#include <cuda_runtime.h>
#include <cuda_bf16.h>
#include <cstdint>

// ---------------- problem constants ----------------
#define BN      4096
#define KN      20
#define D_EMB   128
#define D_FEAT  172
#define D_TIME  100
#define XCOLS   448              // X row stride: node 172 | edge 172 | time 100 | pad 4
#define KTOT    448
#define GROWS   32               // GEMM rows per block
#define XS_ST   34               // xs k-stride (floats): even (8B pairs), mild write conflicts only
#define WCHUNK  16               // k per W smem chunk
#define NCHUNK  (KTOT / WCHUNK)  // 28
#define XS_FLOATS (KTOT * XS_ST)             // 15232
#define WS_FLOATS (2 * WCHUNK * D_EMB)       // 4096
#define GSMEM_BYTES ((XS_FLOATS + WS_FLOATS) * 4)   // 77312

typedef unsigned long long ull;

// ---------------- device scratch (no allocation allowed) ----------------
__device__ __align__(16) float g_X[(size_t)BN * XCOLS];     // 7.3 MB reduced features
__device__ __align__(16) float g_base[(size_t)BN * D_EMB];  // memory terms
__device__ __align__(16) float g_W[(size_t)KTOT * D_EMB];   // packed [Wn;We;Wt;0]

// ---------------- accurate cos for large fp32 args (validated) ----------------
__device__ __forceinline__ float cos_cw(float x) {
    const float TWO_OVER_PI = 0.63661977236758134f;
    const float P1 = 1.57079625129699707031e+00f;
    const float P2 = 7.54978941586159375e-08f;
    const float P3 = 5.39030252995776477e-15f;
    float n = rintf(x * TWO_OVER_PI);
    float r = fmaf(n, -P1, x);
    r = fmaf(n, -P2, r);
    r = fmaf(n, -P3, r);
    int q = ((int)n) & 3;
    float r2 = r * r;
    float s = fmaf(r2, -1.98412698412698413e-4f, 8.33333333333333322e-3f);
    s = fmaf(r2, s, -1.66666666666666666e-1f);
    s = r * fmaf(r2, s, 1.0f);
    float c = fmaf(r2, 2.48015873015873016e-5f, -1.38888888888888889e-3f);
    c = fmaf(r2, c, 4.16666666666666666e-2f);
    c = fmaf(r2, c, -0.5f);
    c = fmaf(r2, c, 1.0f);
    float v = (q & 1) ? s : c;
    if ((q + 1) & 2) v = -v;
    return v;
}

// ---------------- f32x2 packed helpers ----------------
__device__ __forceinline__ ull dup2(float v) {
    ull r;
    asm("mov.b64 %0, {%1, %1};" : "=l"(r) : "f"(v));
    return r;
}
__device__ __forceinline__ void fma2(ull& d, ull a, ull b) {
    asm("fma.rn.f32x2 %0, %1, %2, %0;" : "+l"(d) : "l"(a), "l"(b));
}
__device__ __forceinline__ void unpack2(ull v, float& lo, float& hi) {
    asm("mov.b64 {%0, %1}, %2;" : "=f"(lo), "=f"(hi) : "l"(v));
}

// ---------------- gather + masked reduce + (first 224 blocks) W pack ----------------
__global__ void __launch_bounds__(256) gather_kernel(
    const float* __restrict__ nf, const float* __restrict__ ef,
    const float* __restrict__ mem,
    const float* __restrict__ ts, const float* __restrict__ ets,
    const float* __restrict__ tw, const float* __restrict__ tb,
    const int* __restrict__ srcn, const int* __restrict__ nbr,
    const int* __restrict__ eidx,
    const float* __restrict__ W_node, const float* __restrict__ W_edge,
    const float* __restrict__ W_time)
{
    const int b = blockIdx.x;
    const int t = threadIdx.x;

    // ---- W pack side-job (replaces prep_W launch) ----
    if (b < (KTOT * D_EMB) / 256) {
        const int i = b * 256 + t;
        const int k = i >> 7;
        const int n = i & 127;
        float v;
        if (k < D_FEAT)                   v = W_node[k * D_EMB + n];
        else if (k < 2 * D_FEAT)          v = W_edge[(k - D_FEAT) * D_EMB + n];
        else if (k < 2 * D_FEAT + D_TIME) v = W_time[(k - 2 * D_FEAT) * D_EMB + n];
        else                              v = 0.f;
        g_W[i] = v;
    }

    __shared__ int   nbr_s[KN];
    __shared__ int   eidx_s[KN];
    __shared__ float del_s[KN];
    __shared__ float msk_s[KN];

    if (t < KN) {
        int nb = nbr[b * KN + t];
        nbr_s[t]  = nb;
        eidx_s[t] = eidx[b * KN + t];
        del_s[t]  = ts[b] - ets[b * KN + t];
        msk_s[t]  = (nb != 0) ? 1.f : 0.f;
    }
    __syncthreads();

    const int task1 = t + 256;
    const bool r0_node = (t < D_FEAT);
    const bool r1_edge = (task1 < 344);
    const bool r1_time = (task1 >= 344 && task1 < 444);
    const int  j       = task1 - 344;
    const bool r2_mem  = (t < 60);
    float wj = 0.f, bj = 0.f;
    if (r1_time) { wj = tw[j]; bj = tb[j]; }

    float acc0 = 0.f, acc1 = 0.f, acc2 = 0.f;
    float cntf = 0.f;

    #pragma unroll
    for (int k = 0; k < KN; k++) {
        const float m  = msk_s[k];
        const int   nb = nbr_s[k];
        const int   ei = eidx_s[k];
        cntf += m;
        float v0 = r0_node ? __ldg(nf + (size_t)nb * D_FEAT + t)
                           : __ldg(ef + (size_t)ei * D_FEAT + (t - D_FEAT));
        acc0 = fmaf(m, v0, acc0);
        float v1;
        if (r1_edge)      v1 = __ldg(ef + (size_t)ei * D_FEAT + (task1 - D_FEAT));
        else if (r1_time) v1 = cos_cw(__fadd_rn(__fmul_rn(del_s[k], wj), bj));
        else              v1 = __ldg(mem + (size_t)nb * D_EMB + (task1 - 444));
        acc1 = fmaf(m, v1, acc1);
        if (r2_mem) acc2 = fmaf(m, __ldg(mem + (size_t)nb * D_EMB + (t + 68)), acc2);
    }

    const float inv = 1.f / fmaxf(cntf, 1.f);
    const int src = srcn[b];

    {
        float v = acc0 * inv;
        if (r0_node) v += __ldg(nf + (size_t)src * D_FEAT + t);
        g_X[(size_t)b * XCOLS + t] = v;
    }
    if (task1 < 444) {
        float v = acc1 * inv;
        if (r1_time) v += cos_cw(bj);   // src time embedding: cos(0*w + b)
        g_X[(size_t)b * XCOLS + task1] = v;
    } else {
        const int c = task1 - 444;
        g_base[(size_t)b * D_EMB + c] = __ldg(mem + (size_t)src * D_EMB + c) + acc1 * inv;
    }
    if (r2_mem) {
        const int c = t + 68;
        g_base[(size_t)b * D_EMB + c] = __ldg(mem + (size_t)src * D_EMB + c) + acc2 * inv;
    }
    if (t < 4) g_X[(size_t)b * XCOLS + 444 + t] = 0.f;
}

// ---------------- f32x2 GEMM v3: W staged through smem, 32 rows/block ----------------
// 256 thr, 8 warps; warp w owns rows m0+4w..m0+4w+3 (2 f32x2 row-pairs), lane = 4 cols.
__global__ void __launch_bounds__(256) gemm_kernel(float* __restrict__ out)
{
    extern __shared__ float sm[];
    float* xs = sm;                    // [KTOT][XS_ST] transposed X tile
    float* ws = sm + XS_FLOATS;        // double-buffered W chunks [2][WCHUNK*128]

    const int tid = threadIdx.x;
    const int wid = tid >> 5;
    const int lane = tid & 31;
    const int c0 = lane * 4;
    const int r0 = wid * 4;
    const int m0 = blockIdx.x * GROWS;

    // ---- fill transposed X tile (coalesced LDG.128, strided STS) ----
    for (int idx = tid; idx < GROWS * (XCOLS / 4); idx += 256) {
        const int row = idx / (XCOLS / 4);
        const int c4 = idx - row * (XCOLS / 4);
        float4 x = *(const float4*)&g_X[(size_t)(m0 + row) * XCOLS + c4 * 4];
        const int kb = c4 * 4;
        xs[(kb + 0) * XS_ST + row] = x.x;
        xs[(kb + 1) * XS_ST + row] = x.y;
        xs[(kb + 2) * XS_ST + row] = x.z;
        xs[(kb + 3) * XS_ST + row] = x.w;
    }

    // ---- prologue: load W chunk 0 into regs, stage to buf 0 ----
    const float4* W4 = (const float4*)g_W;
    float4 p0 = W4[2 * tid];
    float4 p1 = W4[2 * tid + 1];
    ((float4*)ws)[2 * tid] = p0;
    ((float4*)ws)[2 * tid + 1] = p1;
    __syncthreads();

    ull acc[8];
    #pragma unroll
    for (int i = 0; i < 8; i++) acc[i] = 0ULL;

    #pragma unroll 1
    for (int c = 0; c < NCHUNK; c++) {
        // prefetch next chunk into regs (overlaps compute below)
        if (c + 1 < NCHUNK) {
            const int base = (c + 1) * WCHUNK * (D_EMB / 4);
            p0 = W4[base + 2 * tid];
            p1 = W4[base + 2 * tid + 1];
        }
        const float* wc = ws + (c & 1) * (WCHUNK * D_EMB);
        #pragma unroll
        for (int i = 0; i < WCHUNK; i++) {
            const float4 wv = *(const float4*)&wc[i * D_EMB + c0];
            const int k = c * WCHUNK + i;
            ull x01 = *(const ull*)&xs[k * XS_ST + r0];       // broadcast
            ull x23 = *(const ull*)&xs[k * XS_ST + r0 + 2];   // broadcast
            ull w0 = dup2(wv.x), w1 = dup2(wv.y), w2 = dup2(wv.z), w3 = dup2(wv.w);
            fma2(acc[0], x01, w0);
            fma2(acc[1], x01, w1);
            fma2(acc[2], x01, w2);
            fma2(acc[3], x01, w3);
            fma2(acc[4], x23, w0);
            fma2(acc[5], x23, w1);
            fma2(acc[6], x23, w2);
            fma2(acc[7], x23, w3);
        }
        if (c + 1 < NCHUNK) {
            float4* wn = (float4*)(ws + ((c + 1) & 1) * (WCHUNK * D_EMB));
            wn[2 * tid] = p0;
            wn[2 * tid + 1] = p1;
        }
        __syncthreads();
    }

    // ---- epilogue: unpack, add base, store ----
    #pragma unroll
    for (int p = 0; p < 2; p++) {
        float l0, h0, l1, h1, l2, h2, l3, h3;
        unpack2(acc[p * 4 + 0], l0, h0);
        unpack2(acc[p * 4 + 1], l1, h1);
        unpack2(acc[p * 4 + 2], l2, h2);
        unpack2(acc[p * 4 + 3], l3, h3);
        const size_t rA = (size_t)(m0 + r0 + 2 * p) * D_EMB + c0;
        const size_t rB = rA + D_EMB;
        float4 bA = *(const float4*)&g_base[rA];
        float4 bB = *(const float4*)&g_base[rB];
        *(float4*)&out[rA] = make_float4(l0 + bA.x, l1 + bA.y, l2 + bA.z, l3 + bA.w);
        *(float4*)&out[rB] = make_float4(h0 + bB.x, h1 + bB.y, h2 + bB.z, h3 + bB.w);
    }
}

extern "C" void kernel_launch(void* const* d_in, const int* in_sizes, int n_in,
                              void* d_out, int out_size) {
    const float* node_features = (const float*)d_in[0];
    const float* edge_features = (const float*)d_in[1];
    const float* memory        = (const float*)d_in[2];
    const float* timestamps    = (const float*)d_in[3];
    const float* edge_times    = (const float*)d_in[4];
    const float* time_w        = (const float*)d_in[5];
    const float* time_b        = (const float*)d_in[6];
    const float* W_node        = (const float*)d_in[7];
    const float* W_edge        = (const float*)d_in[8];
    const float* W_time        = (const float*)d_in[9];
    const int*   source_nodes  = (const int*)d_in[10];
    const int*   neighbors     = (const int*)d_in[11];
    const int*   edge_idxs     = (const int*)d_in[12];
    float* out = (float*)d_out;

    static int smem_set = 0;
    if (!smem_set) {
        cudaFuncSetAttribute(gemm_kernel, cudaFuncAttributeMaxDynamicSharedMemorySize,
                             GSMEM_BYTES);
        smem_set = 1;
    }

    gather_kernel<<<BN, 256>>>(node_features, edge_features, memory,
                               timestamps, edge_times, time_w, time_b,
                               source_nodes, neighbors, edge_idxs,
                               W_node, W_edge, W_time);
    gemm_kernel<<<BN / GROWS, 256, GSMEM_BYTES>>>(out);
}

// round 6
// speedup vs baseline: 7.0434x; 1.4836x over previous
#include <cuda_runtime.h>
#include <cuda_bf16.h>
#include <cstdint>

// ---------------- problem constants ----------------
#define BN      4096
#define KN      20
#define D_EMB   128
#define D_FEAT  172
#define D_TIME  100
#define XCOLS   448              // X row stride: node 172 | edge 172 | time 100 | pad 4
#define KTOT    448
#define GROWS   16               // GEMM rows per block
#define XS_ST   18               // xs k-stride (floats): even -> 8B-aligned row pairs
#define WCHUNK  16               // k per W smem chunk
#define NCHUNK  (KTOT / WCHUNK)  // 28
#define XS_FLOATS (KTOT * XS_ST)             // 8064
#define WS_FLOATS (2 * WCHUNK * D_EMB)       // 4096
#define GSMEM_BYTES ((XS_FLOATS + WS_FLOATS) * 4)   // 48640 (< 49152 default)

typedef unsigned long long ull;

// ---------------- device scratch (no allocation allowed) ----------------
__device__ __align__(16) float g_X[(size_t)BN * XCOLS];     // 7.3 MB reduced features
__device__ __align__(16) float g_base[(size_t)BN * D_EMB];  // memory terms
__device__ __align__(16) float g_W[(size_t)KTOT * D_EMB];   // packed [Wn;We;Wt;0]

// ---------------- accurate cos for large fp32 args (validated) ----------------
__device__ __forceinline__ float cos_cw(float x) {
    const float TWO_OVER_PI = 0.63661977236758134f;
    const float P1 = 1.57079625129699707031e+00f;
    const float P2 = 7.54978941586159375e-08f;
    const float P3 = 5.39030252995776477e-15f;
    float n = rintf(x * TWO_OVER_PI);
    float r = fmaf(n, -P1, x);
    r = fmaf(n, -P2, r);
    r = fmaf(n, -P3, r);
    int q = ((int)n) & 3;
    float r2 = r * r;
    float s = fmaf(r2, -1.98412698412698413e-4f, 8.33333333333333322e-3f);
    s = fmaf(r2, s, -1.66666666666666666e-1f);
    s = r * fmaf(r2, s, 1.0f);
    float c = fmaf(r2, 2.48015873015873016e-5f, -1.38888888888888889e-3f);
    c = fmaf(r2, c, 4.16666666666666666e-2f);
    c = fmaf(r2, c, -0.5f);
    c = fmaf(r2, c, 1.0f);
    float v = (q & 1) ? s : c;
    if ((q + 1) & 2) v = -v;
    return v;
}

// ---------------- f32x2 packed helpers ----------------
__device__ __forceinline__ ull dup2(float v) {
    ull r;
    asm("mov.b64 %0, {%1, %1};" : "=l"(r) : "f"(v));
    return r;
}
__device__ __forceinline__ void fma2(ull& d, ull a, ull b) {
    asm("fma.rn.f32x2 %0, %1, %2, %0;" : "+l"(d) : "l"(a), "l"(b));
}
__device__ __forceinline__ void unpack2(ull v, float& lo, float& hi) {
    asm("mov.b64 {%0, %1}, %2;" : "=f"(lo), "=f"(hi) : "l"(v));
}

// ---------------- gather v2: float4 gathers + concurrent cos tasks ----------------
// Tasks: t<43 node float4 | t<86 edge float4 | t<118 mem float4 | t<218 time scalar | t<222 pad
__global__ void __launch_bounds__(256) gather_kernel(
    const float* __restrict__ nf, const float* __restrict__ ef,
    const float* __restrict__ mem,
    const float* __restrict__ ts, const float* __restrict__ ets,
    const float* __restrict__ tw, const float* __restrict__ tb,
    const int* __restrict__ srcn, const int* __restrict__ nbr,
    const int* __restrict__ eidx,
    const float* __restrict__ W_node, const float* __restrict__ W_edge,
    const float* __restrict__ W_time)
{
    const int b = blockIdx.x;
    const int t = threadIdx.x;

    // ---- W pack side-job on first 224 blocks (no extra launch) ----
    if (b < (KTOT * D_EMB) / 256) {
        const int i = b * 256 + t;
        const int k = i >> 7;
        const int n = i & 127;
        float v;
        if (k < D_FEAT)                   v = W_node[k * D_EMB + n];
        else if (k < 2 * D_FEAT)          v = W_edge[(k - D_FEAT) * D_EMB + n];
        else if (k < 2 * D_FEAT + D_TIME) v = W_time[(k - 2 * D_FEAT) * D_EMB + n];
        else                              v = 0.f;
        g_W[i] = v;
    }

    __shared__ int   nbr_s[KN];
    __shared__ int   eidx_s[KN];
    __shared__ float del_s[KN];
    __shared__ float msk_s[KN];

    if (t < KN) {
        int nb = nbr[b * KN + t];
        nbr_s[t]  = nb;
        eidx_s[t] = eidx[b * KN + t];
        del_s[t]  = ts[b] - ets[b * KN + t];
        msk_s[t]  = (nb != 0) ? 1.f : 0.f;
    }
    __syncthreads();

    // masked-neighbor count (cheap; every thread computes it)
    float cntf = 0.f;
    #pragma unroll
    for (int k = 0; k < KN; k++) cntf += msk_s[k];
    const float inv = 1.f / fmaxf(cntf, 1.f);
    const int src = srcn[b];

    if (t < 118) {
        // ---- uniform-path float4 gather-reduce ----
        const bool is_node = (t < 43);
        const bool is_edge = (t >= 43 && t < 86);
        const float* bp;
        int stride, colo;
        const int* rs;
        if (is_node)      { bp = nf;  stride = D_FEAT; colo = 4 * t;        rs = nbr_s; }
        else if (is_edge) { bp = ef;  stride = D_FEAT; colo = 4 * (t - 43); rs = eidx_s; }
        else              { bp = mem; stride = D_EMB;  colo = 4 * (t - 86); rs = nbr_s; }

        float4 acc = make_float4(0.f, 0.f, 0.f, 0.f);
        #pragma unroll
        for (int k = 0; k < KN; k++) {
            const float m = msk_s[k];
            const float4 v = __ldg((const float4*)(bp + (size_t)rs[k] * stride + colo));
            acc.x = fmaf(m, v.x, acc.x);
            acc.y = fmaf(m, v.y, acc.y);
            acc.z = fmaf(m, v.z, acc.z);
            acc.w = fmaf(m, v.w, acc.w);
        }
        acc.x *= inv; acc.y *= inv; acc.z *= inv; acc.w *= inv;

        if (is_node) {
            const float4 sv = __ldg((const float4*)(nf + (size_t)src * D_FEAT + colo));
            acc.x += sv.x; acc.y += sv.y; acc.z += sv.z; acc.w += sv.w;
            *(float4*)&g_X[(size_t)b * XCOLS + colo] = acc;
        } else if (is_edge) {
            *(float4*)&g_X[(size_t)b * XCOLS + D_FEAT + colo] = acc;
        } else {
            const float4 sv = __ldg((const float4*)(mem + (size_t)src * D_EMB + colo));
            acc.x += sv.x; acc.y += sv.y; acc.z += sv.z; acc.w += sv.w;
            *(float4*)&g_base[(size_t)b * D_EMB + colo] = acc;
        }
    } else if (t < 218) {
        // ---- time-encoding column: sum_k cos(delta_k * w_j + b_j), + src cos(b_j) ----
        const int j = t - 118;
        const float wj = tw[j];
        const float bj = tb[j];
        float a = 0.f;
        #pragma unroll
        for (int k = 0; k < KN; k++) {
            float v = cos_cw(__fadd_rn(__fmul_rn(del_s[k], wj), bj));
            a = fmaf(msk_s[k], v, a);
        }
        g_X[(size_t)b * XCOLS + 344 + j] = a * inv + cos_cw(bj);
    } else if (t < 222) {
        g_X[(size_t)b * XCOLS + 444 + (t - 218)] = 0.f;   // pad cols
    }
}

// ---------------- f32x2 GEMM v4: 16 rows/block, 128 thr, 4 CTAs/SM ----------------
// warp w owns rows m0+4w..m0+4w+3 (2 f32x2 row-pairs), lane = 4 cols.
__global__ void __launch_bounds__(128) gemm_kernel(float* __restrict__ out)
{
    extern __shared__ float sm[];
    float* xs = sm;                    // [KTOT][XS_ST] transposed X tile
    float* ws = sm + XS_FLOATS;        // double-buffered W chunks [2][WCHUNK*128]

    const int tid = threadIdx.x;
    const int wid = tid >> 5;
    const int lane = tid & 31;
    const int c0 = lane * 4;
    const int r0 = wid * 4;
    const int m0 = blockIdx.x * GROWS;

    // ---- fill transposed X tile (coalesced LDG.128, strided STS) ----
    for (int idx = tid; idx < GROWS * (XCOLS / 4); idx += 128) {
        const int row = idx / (XCOLS / 4);
        const int c4 = idx - row * (XCOLS / 4);
        float4 x = *(const float4*)&g_X[(size_t)(m0 + row) * XCOLS + c4 * 4];
        const int kb = c4 * 4;
        xs[(kb + 0) * XS_ST + row] = x.x;
        xs[(kb + 1) * XS_ST + row] = x.y;
        xs[(kb + 2) * XS_ST + row] = x.z;
        xs[(kb + 3) * XS_ST + row] = x.w;
    }

    // ---- prologue: W chunk 0 -> regs -> buf 0 (thread loads 4 float4, interleaved) ----
    const float4* W4 = (const float4*)g_W;
    float4 p[4];
    #pragma unroll
    for (int i = 0; i < 4; i++) p[i] = W4[tid + i * 128];
    {
        float4* w0 = (float4*)ws;
        #pragma unroll
        for (int i = 0; i < 4; i++) w0[tid + i * 128] = p[i];
    }
    __syncthreads();

    ull acc[8];
    #pragma unroll
    for (int i = 0; i < 8; i++) acc[i] = 0ULL;

    #pragma unroll 1
    for (int c = 0; c < NCHUNK; c++) {
        // prefetch next chunk into regs (overlaps compute)
        if (c + 1 < NCHUNK) {
            const int base = (c + 1) * (WCHUNK * D_EMB / 4);
            #pragma unroll
            for (int i = 0; i < 4; i++) p[i] = W4[base + tid + i * 128];
        }
        const float* wc = ws + (c & 1) * (WCHUNK * D_EMB);
        #pragma unroll
        for (int i = 0; i < WCHUNK; i++) {
            const float4 wv = *(const float4*)&wc[i * D_EMB + c0];
            const int k = c * WCHUNK + i;
            ull x01 = *(const ull*)&xs[k * XS_ST + r0];       // broadcast LDS.64
            ull x23 = *(const ull*)&xs[k * XS_ST + r0 + 2];   // broadcast LDS.64
            ull w0 = dup2(wv.x), w1 = dup2(wv.y), w2 = dup2(wv.z), w3 = dup2(wv.w);
            fma2(acc[0], x01, w0);
            fma2(acc[1], x01, w1);
            fma2(acc[2], x01, w2);
            fma2(acc[3], x01, w3);
            fma2(acc[4], x23, w0);
            fma2(acc[5], x23, w1);
            fma2(acc[6], x23, w2);
            fma2(acc[7], x23, w3);
        }
        if (c + 1 < NCHUNK) {
            float4* wn = (float4*)(ws + ((c + 1) & 1) * (WCHUNK * D_EMB));
            #pragma unroll
            for (int i = 0; i < 4; i++) wn[tid + i * 128] = p[i];
        }
        __syncthreads();
    }

    // ---- epilogue: unpack, add base, store ----
    #pragma unroll
    for (int pq = 0; pq < 2; pq++) {
        float l0, h0, l1, h1, l2, h2, l3, h3;
        unpack2(acc[pq * 4 + 0], l0, h0);
        unpack2(acc[pq * 4 + 1], l1, h1);
        unpack2(acc[pq * 4 + 2], l2, h2);
        unpack2(acc[pq * 4 + 3], l3, h3);
        const size_t rA = (size_t)(m0 + r0 + 2 * pq) * D_EMB + c0;
        const size_t rB = rA + D_EMB;
        float4 bA = *(const float4*)&g_base[rA];
        float4 bB = *(const float4*)&g_base[rB];
        *(float4*)&out[rA] = make_float4(l0 + bA.x, l1 + bA.y, l2 + bA.z, l3 + bA.w);
        *(float4*)&out[rB] = make_float4(h0 + bB.x, h1 + bB.y, h2 + bB.z, h3 + bB.w);
    }
}

extern "C" void kernel_launch(void* const* d_in, const int* in_sizes, int n_in,
                              void* d_out, int out_size) {
    const float* node_features = (const float*)d_in[0];
    const float* edge_features = (const float*)d_in[1];
    const float* memory        = (const float*)d_in[2];
    const float* timestamps    = (const float*)d_in[3];
    const float* edge_times    = (const float*)d_in[4];
    const float* time_w        = (const float*)d_in[5];
    const float* time_b        = (const float*)d_in[6];
    const float* W_node        = (const float*)d_in[7];
    const float* W_edge        = (const float*)d_in[8];
    const float* W_time        = (const float*)d_in[9];
    const int*   source_nodes  = (const int*)d_in[10];
    const int*   neighbors     = (const int*)d_in[11];
    const int*   edge_idxs     = (const int*)d_in[12];
    float* out = (float*)d_out;

    gather_kernel<<<BN, 256>>>(node_features, edge_features, memory,
                               timestamps, edge_times, time_w, time_b,
                               source_nodes, neighbors, edge_idxs,
                               W_node, W_edge, W_time);
    gemm_kernel<<<BN / GROWS, 128, GSMEM_BYTES>>>(out);
}